// round 8
// baseline (speedup 1.0000x reference)
#include <cuda_runtime.h>
#include <cuda_bf16.h>
#include <math.h>
#include <stdint.h>

#define NR 12288
#define KD 512
#define FD 128
#define NB 8192
#define BLO (-6.0f)
#define BHI (6.0f)
#define NCH 96
#define CH 128

// ---------------- device scratch ----------------
__device__ __nv_bfloat16 g_wh[FD * KD];
__device__ __nv_bfloat16 g_wl[FD * KD];
__device__ float g_z[NR * FD];
__device__ float g_zp[NR * FD];
__device__ float g_s[NR];
__device__ float g_t[NR];
__device__ int   g_cnt[NB];
__device__ int   g_bstart[NB + 1];
__device__ int   g_cursor[NB];
__device__ float g_tp[NR];
__device__ float g_etp[NR];
__device__ float g_chZ[NCH * FD];
__device__ float g_chEZ[NCH * FD];
__device__ float g_chE[NCH];
__device__ float g_ofZ[NCH * FD];
__device__ float g_ofEZ[NCH * FD];
__device__ float g_ofE[NCH];
__device__ float g_PZ[(NR + 1) * FD];
__device__ float g_SEZ[(NR + 1) * FD];
__device__ float g_SE[NR + 1];

__device__ __forceinline__ int bucket_of(float t) {
    float u = (t - BLO) * ((float)NB / (BHI - BLO));
    int b = (int)floorf(u);
    b = b < 0 ? 0 : b;
    b = b > NB - 1 ? NB - 1 : b;
    return b;
}

__device__ __forceinline__ uint32_t smem_u32(const void* p) {
    uint32_t a;
    asm("{ .reg .u64 t; cvta.to.shared.u64 t, %1; cvt.u32.u64 %0, t; }" : "=r"(a) : "l"(p));
    return a;
}

#define LDSM4(r, a) \
    asm volatile("ldmatrix.sync.aligned.m8n8.x4.shared.b16 {%0,%1,%2,%3}, [%4];" \
        : "=r"((r)[0]), "=r"((r)[1]), "=r"((r)[2]), "=r"((r)[3]) : "r"(a))

#define MMA16816(d, a, b0, b1) \
    asm volatile("mma.sync.aligned.m16n8k16.row.col.f32.bf16.bf16.f32 " \
        "{%0,%1,%2,%3},{%4,%5,%6,%7},{%8,%9},{%0,%1,%2,%3};" \
        : "+f"((d)[0]), "+f"((d)[1]), "+f"((d)[2]), "+f"((d)[3]) \
        : "r"((a)[0]), "r"((a)[1]), "r"((a)[2]), "r"((a)[3]), "r"(b0), "r"(b1))

__device__ __forceinline__ uint32_t packbf(__nv_bfloat16 a, __nv_bfloat16 b) {
    return (uint32_t)__bfloat16_as_ushort(a) | ((uint32_t)__bfloat16_as_ushort(b) << 16);
}

// ---------------- 1. weight-norm -> bf16 split, zero histogram -------------
__global__ void k_w(const float* __restrict__ v, const float* __restrict__ g) {
    int r = blockIdx.x, t = threadIdx.x;
    int gi = r * 64 + t;
    if (gi < NB) g_cnt[gi] = 0;
    float ss = 0.f;
    for (int c = t; c < KD; c += 128) { float a = v[r * KD + c]; ss += a * a; }
    __shared__ float red[4];
    #pragma unroll
    for (int o = 16; o; o >>= 1) ss += __shfl_xor_sync(0xffffffffu, ss, o);
    if ((t & 31) == 0) red[t >> 5] = ss;
    __syncthreads();
    float tot = red[0] + red[1] + red[2] + red[3];
    float sc = g[r] / sqrtf(tot);
    for (int c = t; c < KD; c += 128) {
        float wv = v[r * KD + c] * sc;
        __nv_bfloat16 hi = __float2bfloat16(wv);
        g_wh[r * KD + c] = hi;
        g_wl[r * KD + c] = __float2bfloat16(wv - __bfloat162float(hi));
    }
}

// ---------------- 2. mma.sync bf16-split GEMM + fused epilogue -------------
// CTA: 64(M) x 128(N), 256 threads = 8 warps (2M x 4N), warp 32x32.
// 192 CTAs, 2 CTAs/SM resident -> all SMs busy, cross-CTA phase overlap.
#define RSTR 144
#define SA_H 0
#define SA_L (64 * RSTR)
#define SB_H (2 * 64 * RSTR)
#define SB_L (2 * 64 * RSTR + 128 * RSTR)
#define SP_S (2 * 64 * RSTR + 2 * 128 * RSTR)
#define SP_T (SP_S + 1024)
#define SM_TOT (SP_T + 1024)

__global__ void __launch_bounds__(256, 2)
k_gemm(const float* __restrict__ x, const float* __restrict__ bias,
       const float* __restrict__ att) {
    extern __shared__ char smem[];
    uint32_t sb = smem_u32(smem);
    int tid = threadIdx.x, lane = tid & 31, wid = tid >> 5;
    int m0 = blockIdx.x * 64;
    int warp_m = wid & 1, warp_n = wid >> 1;

    float acc[2][4][4];
    #pragma unroll
    for (int i = 0; i < 2; i++)
        #pragma unroll
        for (int j = 0; j < 4; j++)
            #pragma unroll
            for (int q = 0; q < 4; q++) acc[i][j][q] = 0.f;

    // A loading: 64 rows x 64 cols per chunk, 16 elems/thread
    int lra = tid >> 2, lca = (tid & 3) * 16;
    const float* xrow = x + (size_t)(m0 + lra) * KD + lca;
    char* arow_h = smem + SA_H + lra * RSTR + lca * 2;
    char* arow_l = smem + SA_L + lra * RSTR + lca * 2;
    // B loading: 128 rows x 64 cols per chunk, 32 elems/thread
    int lrb = tid >> 1, lcb = (tid & 1) * 32;
    const __nv_bfloat16* whp = g_wh + (size_t)lrb * KD + lcb;
    const __nv_bfloat16* wlp = g_wl + (size_t)lrb * KD + lcb;
    char* brow_h = smem + SB_H + lrb * RSTR + lcb * 2;
    char* brow_l = smem + SB_L + lrb * RSTR + lcb * 2;

    int a_rb = warp_m * 32 + (lane & 15);
    int a_c  = (lane & 16) ? 8 : 0;
    int b_rb = warp_n * 32 + (lane & 7) + ((lane & 16) ? 8 : 0);
    int b_c  = (lane & 8) ? 8 : 0;

    float4 xr[4];
    uint4 whr[4], wlr[4];
    // prefetch chunk 0
    #pragma unroll
    for (int j = 0; j < 4; j++) xr[j] = *(const float4*)(xrow + j * 4);
    #pragma unroll
    for (int j = 0; j < 4; j++) {
        whr[j] = *(const uint4*)(whp + j * 8);
        wlr[j] = *(const uint4*)(wlp + j * 8);
    }

    for (int c = 0; c < 8; c++) {
        // store staged regs to smem (convert x to bf16 split)
        #pragma unroll
        for (int j = 0; j < 4; j++) {
            float4 f = xr[j];
            __nv_bfloat16 h0 = __float2bfloat16(f.x), h1 = __float2bfloat16(f.y);
            __nv_bfloat16 h2 = __float2bfloat16(f.z), h3 = __float2bfloat16(f.w);
            __nv_bfloat16 l0 = __float2bfloat16(f.x - __bfloat162float(h0));
            __nv_bfloat16 l1 = __float2bfloat16(f.y - __bfloat162float(h1));
            __nv_bfloat16 l2 = __float2bfloat16(f.z - __bfloat162float(h2));
            __nv_bfloat16 l3 = __float2bfloat16(f.w - __bfloat162float(h3));
            *(uint2*)(arow_h + j * 8) = make_uint2(packbf(h0, h1), packbf(h2, h3));
            *(uint2*)(arow_l + j * 8) = make_uint2(packbf(l0, l1), packbf(l2, l3));
        }
        #pragma unroll
        for (int j = 0; j < 4; j++) {
            *(uint4*)(brow_h + j * 16) = whr[j];
            *(uint4*)(brow_l + j * 16) = wlr[j];
        }
        __syncthreads();

        // prefetch next chunk while MMAs run
        if (c < 7) {
            int k1 = (c + 1) * 64;
            #pragma unroll
            for (int j = 0; j < 4; j++) xr[j] = *(const float4*)(xrow + k1 + j * 4);
            #pragma unroll
            for (int j = 0; j < 4; j++) {
                whr[j] = *(const uint4*)(whp + k1 + j * 8);
                wlr[j] = *(const uint4*)(wlp + k1 + j * 8);
            }
        }

        #pragma unroll
        for (int ks = 0; ks < 4; ks++) {
            int ko = ks * 16;
            uint32_t ah[2][4], al[2][4];
            #pragma unroll
            for (int mf = 0; mf < 2; mf++) {
                uint32_t aa = sb + (a_rb + mf * 16) * RSTR + (ko + a_c) * 2;
                LDSM4(ah[mf], aa + SA_H);
                LDSM4(al[mf], aa + SA_L);
            }
            #pragma unroll
            for (int nf2 = 0; nf2 < 2; nf2++) {
                uint32_t bh[4], bl[4];
                uint32_t ba = sb + (b_rb + nf2 * 16) * RSTR + (ko + b_c) * 2;
                LDSM4(bh, ba + SB_H);
                LDSM4(bl, ba + SB_L);
                #pragma unroll
                for (int mf = 0; mf < 2; mf++) {
                    MMA16816(acc[mf][2 * nf2],     ah[mf], bh[0], bh[1]);
                    MMA16816(acc[mf][2 * nf2],     ah[mf], bl[0], bl[1]);
                    MMA16816(acc[mf][2 * nf2],     al[mf], bh[0], bh[1]);
                    MMA16816(acc[mf][2 * nf2 + 1], ah[mf], bh[2], bh[3]);
                    MMA16816(acc[mf][2 * nf2 + 1], ah[mf], bl[2], bl[3]);
                    MMA16816(acc[mf][2 * nf2 + 1], al[mf], bh[2], bh[3]);
                }
            }
        }
        __syncthreads();
    }

    // epilogue: bias, z store, s/t partials
    #pragma unroll
    for (int r4 = 0; r4 < 4; r4++) {
        int mf = r4 >> 1, half = r4 & 1;
        int rloc = warp_m * 32 + mf * 16 + half * 8 + (lane >> 2);
        int row_g = m0 + rloc;
        float sp = 0.f, tp = 0.f;
        #pragma unroll
        for (int nf = 0; nf < 4; nf++) {
            int col = warp_n * 32 + nf * 8 + (lane & 3) * 2;
            float z0 = acc[mf][nf][half * 2]     + bias[col];
            float z1 = acc[mf][nf][half * 2 + 1] + bias[col + 1];
            *(float2*)(g_z + (size_t)row_g * FD + col) = make_float2(z0, z1);
            sp = fmaf(z0, att[col], fmaf(z1, att[col + 1], sp));
            tp = fmaf(z0, att[FD + col], fmaf(z1, att[FD + col + 1], tp));
        }
        sp += __shfl_xor_sync(0xffffffffu, sp, 1);
        sp += __shfl_xor_sync(0xffffffffu, sp, 2);
        tp += __shfl_xor_sync(0xffffffffu, tp, 1);
        tp += __shfl_xor_sync(0xffffffffu, tp, 2);
        if ((lane & 3) == 0) {
            *(float*)(smem + SP_S + (warp_n * 64 + rloc) * 4) = sp;
            *(float*)(smem + SP_T + (warp_n * 64 + rloc) * 4) = tp;
        }
    }
    __syncthreads();
    if (tid < 64) {
        float s = 0.f, t = 0.f;
        #pragma unroll
        for (int q = 0; q < 4; q++) {
            s += *(float*)(smem + SP_S + (q * 64 + tid) * 4);
            t += *(float*)(smem + SP_T + (q * 64 + tid) * 4);
        }
        g_s[m0 + tid] = s;
        g_t[m0 + tid] = t;
        atomicAdd(&g_cnt[bucket_of(t)], 1);
    }
}

// ---------------- 3. parallel bucket prefix ----------------
__global__ void k_prefix() {
    __shared__ int wsum[8];
    int t = threadIdx.x, lane = t & 31, wid = t >> 5;
    int c[32];
    const int4* c4 = (const int4*)g_cnt;
    int s = 0;
    #pragma unroll
    for (int i = 0; i < 8; i++) {
        int4 v = c4[t * 8 + i];
        c[4 * i] = v.x; c[4 * i + 1] = v.y; c[4 * i + 2] = v.z; c[4 * i + 3] = v.w;
        s += v.x + v.y + v.z + v.w;
    }
    int sc = s;
    #pragma unroll
    for (int o = 1; o < 32; o <<= 1) {
        int n = __shfl_up_sync(0xffffffffu, sc, o);
        if (lane >= o) sc += n;
    }
    if (lane == 31) wsum[wid] = sc;
    __syncthreads();
    int woff = 0;
    #pragma unroll
    for (int i = 0; i < 8; i++) if (i < wid) woff += wsum[i];
    int run = woff + sc - s;
    #pragma unroll
    for (int i = 0; i < 32; i++) {
        g_bstart[t * 32 + i] = run;
        g_cursor[t * 32 + i] = run;
        run += c[i];
    }
    if (t == 255) g_bstart[NB] = NR;
}

// ---------------- 4. fused scatter + permuted-z materialize ----------------
__global__ void k_scatter() {
    int gw = (blockIdx.x * blockDim.x + threadIdx.x) >> 5;
    int lane = threadIdx.x & 31;
    if (gw >= NR) return;
    int slot = 0;
    float tv = 0.f;
    if (lane == 0) {
        tv = g_t[gw];
        slot = atomicAdd(&g_cursor[bucket_of(tv)], 1);
    }
    slot = __shfl_sync(0xffffffffu, slot, 0);
    float4 zv = *(const float4*)(g_z + (size_t)gw * FD + lane * 4);
    *(float4*)(g_zp + (size_t)slot * FD + lane * 4) = zv;
    if (lane == 0) {
        g_tp[slot] = tv;
        g_etp[slot] = expf(tv);
    }
}

// ---------------- 5. chunked scans ----------------
__global__ void k_s1() {
    int c = blockIdx.x, f = threadIdx.x;
    int base = c * CH;
    float aZ = 0.f, aEZ = 0.f, aE = 0.f;
    #pragma unroll 8
    for (int r = 0; r < CH; r++) {
        int m = base + r;
        float et = g_etp[m];
        float zv = g_zp[(size_t)m * FD + f];
        aZ += zv;
        aEZ = fmaf(et, zv, aEZ);
        aE += et;
    }
    g_chZ[c * FD + f] = aZ;
    g_chEZ[c * FD + f] = aEZ;
    if (f == 0) g_chE[c] = aE;
}

__global__ void k_s2() {
    int f = threadIdx.x;
    float run = 0.f;
    #pragma unroll 8
    for (int c = 0; c < NCH; c++) { g_ofZ[c * FD + f] = run; run += g_chZ[c * FD + f]; }
    g_PZ[(size_t)NR * FD + f] = run;
    float re = 0.f;
    #pragma unroll 8
    for (int c = NCH - 1; c >= 0; c--) { g_ofEZ[c * FD + f] = re; re += g_chEZ[c * FD + f]; }
    g_SEZ[(size_t)NR * FD + f] = 0.f;
    if (f == 0) {
        float rE = 0.f;
        for (int c = NCH - 1; c >= 0; c--) { g_ofE[c] = rE; rE += g_chE[c]; }
        g_SE[NR] = 0.f;
    }
}

__global__ void k_s3() {
    int c = blockIdx.x, f = threadIdx.x, base = c * CH;
    float aZ = g_ofZ[c * FD + f];
    #pragma unroll 8
    for (int r = 0; r < CH; r++) {
        int m = base + r;
        g_PZ[(size_t)m * FD + f] = aZ;
        aZ += g_zp[(size_t)m * FD + f];
    }
    float aEZ = g_ofEZ[c * FD + f];
    float aE = g_ofE[c];
    #pragma unroll 8
    for (int r = CH - 1; r >= 0; r--) {
        int m = base + r;
        float et = g_etp[m];
        aEZ = fmaf(et, g_zp[(size_t)m * FD + f], aEZ);
        g_SEZ[(size_t)m * FD + f] = aEZ;
        if (f == 0) { aE += et; g_SE[m] = aE; }
    }
}

// ---------------- 6. per-row combine + row softmax (1 row / block) ---------
__global__ void k_final(float* __restrict__ out) {
    __shared__ float rmax[4], rsum[4];
    int f = threadIdx.x, lane = f & 31, wid = f >> 5;
    int i = blockIdx.x;
    float si = g_s[i];
    float th = -si;
    float es = expf(si);
    int b = bucket_of(th);
    int klo = g_bstart[b], khi = g_bstart[b + 1];
    float D = (float)klo + es * g_SE[khi];
    float num = g_PZ[(size_t)klo * FD + f] + es * g_SEZ[(size_t)khi * FD + f];
    for (int m = klo; m < khi; m++) {
        float tj = g_tp[m];
        float zv = g_zp[(size_t)m * FD + f];
        if (tj <= th) { num += zv; D += 1.f; }
        else { float w = es * g_etp[m]; num = fmaf(w, zv, num); D += w; }
    }
    float z2 = num / D + g_z[(size_t)i * FD + f];
    float mx = z2;
    #pragma unroll
    for (int o = 16; o; o >>= 1) mx = fmaxf(mx, __shfl_xor_sync(0xffffffffu, mx, o));
    if (lane == 0) rmax[wid] = mx;
    __syncthreads();
    mx = fmaxf(fmaxf(rmax[0], rmax[1]), fmaxf(rmax[2], rmax[3]));
    float ex = expf(z2 - mx);
    float sm = ex;
    #pragma unroll
    for (int o = 16; o; o >>= 1) sm += __shfl_xor_sync(0xffffffffu, sm, o);
    if (lane == 0) rsum[wid] = sm;
    __syncthreads();
    sm = rsum[0] + rsum[1] + rsum[2] + rsum[3];
    out[(size_t)i * FD + f] = ex / sm;
}

// ---------------- launch ----------------
extern "C" void kernel_launch(void* const* d_in, const int* in_sizes, int n_in,
                              void* d_out, int out_size) {
    const float* x   = (const float*)d_in[0];
    const float* v   = (const float*)d_in[1];
    const float* g   = (const float*)d_in[2];
    const float* b   = (const float*)d_in[3];
    const float* att = (const float*)d_in[4];
    float* out = (float*)d_out;

    static int smem_set = 0;
    if (!smem_set) {
        cudaFuncSetAttribute(k_gemm, cudaFuncAttributeMaxDynamicSharedMemorySize, SM_TOT);
        smem_set = 1;
    }

    k_w<<<FD, 128>>>(v, g);
    k_gemm<<<NR / 64, 256, SM_TOT>>>(x, b, att);
    k_prefix<<<1, 256>>>();
    k_scatter<<<NR / 8, 256>>>();
    k_s1<<<NCH, FD>>>();
    k_s2<<<1, FD>>>();
    k_s3<<<NCH, FD>>>();
    k_final<<<NR, FD>>>(out);
}